// round 1
// baseline (speedup 1.0000x reference)
#include <cuda_runtime.h>

#define LROW     32768
#define TILE     2048
#define NTHREADS 256
#define CHUNK    8
#define SLOPE    0.1f

// Fused: up-sample x2 (12-tap kaiser-sinc, polyphase) -> LeakyReLU -> down-sample x2.
// Each thread produces 8 consecutive outputs of one row. Phases:
//   E(i) = lrelu( 2*sum_e f[2e]  * x[clamp(i-3+e)] )   == act[2i]
//   O(i) = lrelu( 2*sum_e f[2e+1]* x[clamp(i-2+e)] )   == act[2i+1]
//   out[o] = sum_m dn[2m]*O(o+m-3) + dn[2m+1]*E(o+m-2)
__global__ __launch_bounds__(NTHREADS)
void aa_act_kernel(const float* __restrict__ x,
                   const float* __restrict__ upf,
                   const float* __restrict__ dnf,
                   float* __restrict__ out)
{
    __shared__ __align__(16) float sx[TILE + 12];   // covers x[o0-5 .. o0+TILE+4] (TILE+10 used)

    const int row = blockIdx.y;
    const int o0  = blockIdx.x * TILE;
    const float* xr = x + (size_t)row * LROW;

    // Stage x tile (+halo) into smem with edge clamp; coalesced.
    for (int s = threadIdx.x; s < TILE + 10; s += NTHREADS) {
        int gi = o0 - 5 + s;
        gi = max(0, min(gi, LROW - 1));
        sx[s] = __ldg(xr + gi);
    }

    // Taps (broadcast LDG, L1-hit). Fold the r=2 gain into the up taps.
    float fe[6], fo[6], dn[12];
#pragma unroll
    for (int e = 0; e < 6; ++e) {
        fe[e] = 2.0f * __ldg(upf + 2 * e);
        fo[e] = 2.0f * __ldg(upf + 2 * e + 1);
    }
#pragma unroll
    for (int k = 0; k < 12; ++k) dn[k] = __ldg(dnf + k);

    __syncthreads();

    const int tid = threadIdx.x;
    const int o   = o0 + tid * CHUNK;

    // Per-thread x window x[o-5 .. o+12] via vectorized LDS (avoids 8-way bank conflicts).
    float xv[18];
    {
        const float* base = sx + tid * CHUNK;      // 16B aligned (CHUNK=8 floats)
        float4 a = *(const float4*)(base + 0);
        float4 b = *(const float4*)(base + 4);
        float4 c = *(const float4*)(base + 8);
        float4 d = *(const float4*)(base + 12);
        float2 e = *(const float2*)(base + 16);
        xv[0]=a.x;  xv[1]=a.y;  xv[2]=a.z;  xv[3]=a.w;
        xv[4]=b.x;  xv[5]=b.y;  xv[6]=b.z;  xv[7]=b.w;
        xv[8]=c.x;  xv[9]=c.y;  xv[10]=c.z; xv[11]=c.w;
        xv[12]=d.x; xv[13]=d.y; xv[14]=d.z; xv[15]=d.w;
        xv[16]=e.x; xv[17]=e.y;
    }

    // Both polyphase outputs at slot t read the SAME window xv[t..t+5].
    // E[t] == act[2*(o-2+t)], O[t] == act[2*(o-3+t)+1]
    float E[13], O[13];
#pragma unroll
    for (int t = 0; t < 13; ++t) {
        float se = 0.f, so = 0.f;
#pragma unroll
        for (int e = 0; e < 6; ++e) {
            se = fmaf(fe[e], xv[t + e], se);
            so = fmaf(fo[e], xv[t + e], so);
        }
        E[t] = fmaf(SLOPE, fminf(se, 0.f), fmaxf(se, 0.f));
        O[t] = fmaf(SLOPE, fminf(so, 0.f), fmaxf(so, 0.f));
    }

    // Row-edge fixups: act index clamps to act[0] / act[2L-1].
    if (o == 0) {                         // first thread of first tile only
        float a0 = E[2];                  // act[0]
        E[0] = a0; E[1] = a0;
        O[0] = a0; O[1] = a0; O[2] = a0;
    }
    if (o == LROW - CHUNK) {              // last thread of last tile only
        float aL = O[10];                 // act[2L-1]
        O[11] = aL; O[12] = aL;
        E[10] = aL; E[11] = aL; E[12] = aL;
    }

    // Downsample: out[o+q] = sum_m dn[2m]*O[q+m] + dn[2m+1]*E[q+m]
    float acc[CHUNK];
#pragma unroll
    for (int q = 0; q < CHUNK; ++q) {
        float a = 0.f;
#pragma unroll
        for (int m = 0; m < 6; ++m) {
            a = fmaf(dn[2 * m],     O[q + m], a);
            a = fmaf(dn[2 * m + 1], E[q + m], a);
        }
        acc[q] = a;
    }

    float4* op = (float4*)(out + (size_t)row * LROW + o);
    op[0] = make_float4(acc[0], acc[1], acc[2], acc[3]);
    op[1] = make_float4(acc[4], acc[5], acc[6], acc[7]);
}

extern "C" void kernel_launch(void* const* d_in, const int* in_sizes, int n_in,
                              void* d_out, int out_size)
{
    const float* x   = (const float*)d_in[0];
    const float* upf = (const float*)d_in[1];
    const float* dnf = (const float*)d_in[2];
    float* out = (float*)d_out;

    const int rows = in_sizes[0] / LROW;           // 8*128 = 1024
    dim3 grid(LROW / TILE, rows);
    aa_act_kernel<<<grid, NTHREADS>>>(x, upf, dnf, out);
}

// round 2
// speedup vs baseline: 1.3763x; 1.3763x over previous
#include <cuda_runtime.h>

#define LROW     32768
#define TILE     2048
#define NTHREADS 256
#define CHUNK    8
#define SLOPE    0.1f

// smem covers x[o0-8 .. o0+TILE+15]  (2064 floats = 516 float4, 16B aligned both ends)
#define SSTAGE   (TILE + 16)          // 2064
#define SVEC     (SSTAGE / 4)         // 516

// Fused up-2x (12-tap kaiser-sinc polyphase) -> LeakyReLU -> down-2x.
//   E(i) = lrelu( 2*sum_e f[2e]  * x[clamp(i-3+e)] ) == act[2i]
//   O(i) = lrelu( 2*sum_e f[2e+1]* x[clamp(i-2+e)] ) == act[2i+1]
//   out[o] = sum_m dn[2m]*O(o+m-3) + dn[2m+1]*E(o+m-2)
__global__ __launch_bounds__(NTHREADS)
void aa_act_kernel(const float* __restrict__ x,
                   const float* __restrict__ upf,
                   const float* __restrict__ dnf,
                   float* __restrict__ out)
{
    __shared__ __align__(16) float sx[SSTAGE];

    const int row = blockIdx.y;
    const int o0  = blockIdx.x * TILE;
    const float* xr = x + (size_t)row * LROW;

    const bool edge = (blockIdx.x == 0) | (blockIdx.x == gridDim.x - 1);
    if (!edge) {
        // Interior: 16B-aligned bulk staging, no clamping. MLP_p1 = 3.
        const float4* xr4 = (const float4*)(xr + (o0 - 8));
        float4* sx4 = (float4*)sx;
#pragma unroll
        for (int k = 0; k < 2; ++k)
            sx4[threadIdx.x + k * NTHREADS] = __ldg(xr4 + threadIdx.x + k * NTHREADS);
        if (threadIdx.x < SVEC - 2 * NTHREADS)
            sx4[threadIdx.x + 2 * NTHREADS] = __ldg(xr4 + threadIdx.x + 2 * NTHREADS);
    } else {
        // Row-edge blocks: scalar staging with edge clamp (exact round-1 semantics).
        for (int s = threadIdx.x; s < SSTAGE; s += NTHREADS) {
            int gi = o0 - 8 + s;
            gi = max(0, min(gi, LROW - 1));
            sx[s] = __ldg(xr + gi);
        }
    }

    // Taps (broadcast, L1-hit). Fold the r=2 gain into the up taps.
    float fe[6], fo[6], dn[12];
#pragma unroll
    for (int e = 0; e < 6; ++e) {
        fe[e] = 2.0f * __ldg(upf + 2 * e);
        fo[e] = 2.0f * __ldg(upf + 2 * e + 1);
    }
#pragma unroll
    for (int k = 0; k < 12; ++k) dn[k] = __ldg(dnf + k);

    __syncthreads();

    const int tid = threadIdx.x;
    const int o   = o0 + tid * CHUNK;

    // Per-thread window x[o-8 .. o+15] via 6 aligned LDS.128 (no 8-way conflicts).
    float xv[24];
    {
        const float4* base = (const float4*)(sx + tid * CHUNK);  // 32B-aligned
#pragma unroll
        for (int v = 0; v < 6; ++v) {
            float4 q = base[v];
            xv[4 * v + 0] = q.x; xv[4 * v + 1] = q.y;
            xv[4 * v + 2] = q.z; xv[4 * v + 3] = q.w;
        }
    }

    // Both polyphase outputs at slot t read the SAME window xv[t+3 .. t+8]
    // (xv[j] = x[o-8+j]).  E[t]==act[2*(o-2+t)],  O[t]==act[2*(o-3+t)+1]
    float E[13], O[13];
#pragma unroll
    for (int t = 0; t < 13; ++t) {
        float se = 0.f, so = 0.f;
#pragma unroll
        for (int e = 0; e < 6; ++e) {
            se = fmaf(fe[e], xv[t + 3 + e], se);
            so = fmaf(fo[e], xv[t + 3 + e], so);
        }
        E[t] = fmaf(SLOPE, fminf(se, 0.f), fmaxf(se, 0.f));
        O[t] = fmaf(SLOPE, fminf(so, 0.f), fmaxf(so, 0.f));
    }

    // Row-edge act-index fixups (act clamps to act[0] / act[2L-1]).
    if (o == 0) {
        float a0 = E[2];                  // act[0]
        E[0] = a0; E[1] = a0;
        O[0] = a0; O[1] = a0; O[2] = a0;
    }
    if (o == LROW - CHUNK) {
        float aL = O[10];                 // act[2L-1]
        O[11] = aL; O[12] = aL;
        E[10] = aL; E[11] = aL; E[12] = aL;
    }

    // Downsample: out[o+q] = sum_m dn[2m]*O[q+m] + dn[2m+1]*E[q+m]
    float acc[CHUNK];
#pragma unroll
    for (int q = 0; q < CHUNK; ++q) {
        float a = 0.f;
#pragma unroll
        for (int m = 0; m < 6; ++m) {
            a = fmaf(dn[2 * m],     O[q + m], a);
            a = fmaf(dn[2 * m + 1], E[q + m], a);
        }
        acc[q] = a;
    }

    float4* op = (float4*)(out + (size_t)row * LROW + o);
    op[0] = make_float4(acc[0], acc[1], acc[2], acc[3]);
    op[1] = make_float4(acc[4], acc[5], acc[6], acc[7]);
}

extern "C" void kernel_launch(void* const* d_in, const int* in_sizes, int n_in,
                              void* d_out, int out_size)
{
    const float* x   = (const float*)d_in[0];
    const float* upf = (const float*)d_in[1];
    const float* dnf = (const float*)d_in[2];
    float* out = (float*)d_out;

    const int rows = in_sizes[0] / LROW;           // 8*128 = 1024
    dim3 grid(LROW / TILE, rows);
    aa_act_kernel<<<grid, NTHREADS>>>(x, upf, dnf, out);
}

// round 3
// speedup vs baseline: 1.5786x; 1.1470x over previous
#include <cuda_runtime.h>
#include <cstdint>

#define LROW     32768
#define TILE     2048
#define NTHREADS 256
#define CHUNK    8

#define SSTAGE   (TILE + 16)          // x[o0-8 .. o0+TILE+7] window, 16B aligned
#define SVEC     (SSTAGE / 4)         // 516

// ---- f32x2 packed helpers (sm_100+) ----
__device__ __forceinline__ uint64_t pack2(float lo, float hi) {
    uint64_t r; asm("mov.b64 %0, {%1, %2};" : "=l"(r) : "f"(lo), "f"(hi)); return r;
}
__device__ __forceinline__ uint64_t dup2(float v) { return pack2(v, v); }
__device__ __forceinline__ void unpack2(uint64_t v, float& lo, float& hi) {
    asm("mov.b64 {%0, %1}, %2;" : "=f"(lo), "=f"(hi) : "l"(v));
}
__device__ __forceinline__ uint64_t fma2(uint64_t a, uint64_t b, uint64_t c) {
    uint64_t d; asm("fma.rn.f32x2 %0, %1, %2, %3;" : "=l"(d) : "l"(a), "l"(b), "l"(c)); return d;
}
__device__ __forceinline__ uint64_t mul2(uint64_t a, uint64_t b) {
    uint64_t d; asm("mul.rn.f32x2 %0, %1, %2;" : "=l"(d) : "l"(a), "l"(b)); return d;
}

// Fused up-2x (12-tap polyphase) -> LeakyReLU(0.1) -> down-2x, f32x2-packed.
//   lane0 = E chain (even up phase), lane1 = O chain (odd up phase).
//   lrelu(v) = 0.55*v + 0.45*|v|   (== v for v>=0, 0.1v for v<0)
__global__ __launch_bounds__(NTHREADS)
void aa_act_kernel(const float* __restrict__ x,
                   const float* __restrict__ upf,
                   const float* __restrict__ dnf,
                   float* __restrict__ out)
{
    __shared__ __align__(16) float sx[SSTAGE];

    const int row = blockIdx.y;
    const int o0  = blockIdx.x * TILE;
    const float* xr = x + (size_t)row * LROW;

    const bool edge = (blockIdx.x == 0) | (blockIdx.x == gridDim.x - 1);
    if (!edge) {
        const float4* xr4 = (const float4*)(xr + (o0 - 8));
        float4* sx4 = (float4*)sx;
#pragma unroll
        for (int k = 0; k < 2; ++k)
            sx4[threadIdx.x + k * NTHREADS] = __ldg(xr4 + threadIdx.x + k * NTHREADS);
        if (threadIdx.x < SVEC - 2 * NTHREADS)
            sx4[threadIdx.x + 2 * NTHREADS] = __ldg(xr4 + threadIdx.x + 2 * NTHREADS);
    } else {
        for (int s = threadIdx.x; s < SSTAGE; s += NTHREADS) {
            int gi = o0 - 8 + s;
            gi = max(0, min(gi, LROW - 1));
            sx[s] = __ldg(xr + gi);
        }
    }

    // Packed taps: f2[e] = (2*up[2e], 2*up[2e+1]);  dnp[m] = (dn[2m+1], dn[2m])
    // (lane0 of act pair is E -> multiplied by dn[2m+1]; lane1 is O -> dn[2m]).
    uint64_t f2[6], dnp[6];
#pragma unroll
    for (int e = 0; e < 6; ++e)
        f2[e] = pack2(2.0f * __ldg(upf + 2 * e), 2.0f * __ldg(upf + 2 * e + 1));
#pragma unroll
    for (int m = 0; m < 6; ++m)
        dnp[m] = pack2(__ldg(dnf + 2 * m + 1), __ldg(dnf + 2 * m));

    __syncthreads();

    const int tid = threadIdx.x;
    const int o   = o0 + tid * CHUNK;

    // Window x[o-8 .. o+15] -> lane-duplicated packs xx[j] = (x, x), j=0..23.
    uint64_t xx[24];
    {
        const float4* base = (const float4*)(sx + tid * CHUNK);  // 32B-aligned
#pragma unroll
        for (int v = 0; v < 6; ++v) {
            float4 q = base[v];
            xx[4 * v + 0] = dup2(q.x); xx[4 * v + 1] = dup2(q.y);
            xx[4 * v + 2] = dup2(q.z); xx[4 * v + 3] = dup2(q.w);
        }
    }

    // Up-sample + lrelu, packed.  EO[t] = (E[t], O[t]),
    //   E[t]==act[2*(o-2+t)], O[t]==act[2*(o-3+t)+1]; window xx[t+3 .. t+8].
    const uint64_t c55 = dup2(0.55f), c45 = dup2(0.45f);
    uint64_t EO[13];
#pragma unroll
    for (int t = 0; t < 13; ++t) {
        uint64_t v = mul2(f2[0], xx[t + 3]);
#pragma unroll
        for (int e = 1; e < 6; ++e)
            v = fma2(f2[e], xx[t + 3 + e], v);
        uint64_t av = v & 0x7FFFFFFF7FFFFFFFULL;      // packed |v|
        EO[t] = fma2(c45, av, mul2(c55, v));          // packed lrelu
    }

    // Row-edge act-index fixups (act clamps to act[0] / act[2L-1]).
    if (o == 0) {
        float a0 = __uint_as_float((uint32_t)EO[2]);          // E[2] == act[0]
        uint64_t p = dup2(a0);
        EO[0] = p; EO[1] = p; EO[2] = p;                      // E[2] is already a0
    }
    if (o == LROW - CHUNK) {
        float aL = __uint_as_float((uint32_t)(EO[10] >> 32)); // O[10] == act[2L-1]
        uint64_t p = dup2(aL);
        EO[10] = p; EO[11] = p; EO[12] = p;                   // O[10] is already aL
    }

    // Downsample: out[o+q] = sum_m dn[2m]*O[q+m] + dn[2m+1]*E[q+m]
    float acc[CHUNK];
#pragma unroll
    for (int q = 0; q < CHUNK; ++q) {
        uint64_t a2 = mul2(dnp[0], EO[q]);
#pragma unroll
        for (int m = 1; m < 6; ++m)
            a2 = fma2(dnp[m], EO[q + m], a2);
        float lo, hi; unpack2(a2, lo, hi);
        acc[q] = lo + hi;
    }

    float4* op = (float4*)(out + (size_t)row * LROW + o);
    op[0] = make_float4(acc[0], acc[1], acc[2], acc[3]);
    op[1] = make_float4(acc[4], acc[5], acc[6], acc[7]);
}

extern "C" void kernel_launch(void* const* d_in, const int* in_sizes, int n_in,
                              void* d_out, int out_size)
{
    const float* x   = (const float*)d_in[0];
    const float* upf = (const float*)d_in[1];
    const float* dnf = (const float*)d_in[2];
    float* out = (float*)d_out;

    const int rows = in_sizes[0] / LROW;           // 8*128 = 1024
    dim3 grid(LROW / TILE, rows);
    aa_act_kernel<<<grid, NTHREADS>>>(x, upf, dnf, out);
}

// round 4
// speedup vs baseline: 1.7729x; 1.1231x over previous
#include <cuda_runtime.h>
#include <cstdint>

#define LROW     32768
#define TILE     2048
#define NTHREADS 256
#define CHUNK    8

// ---- f32x2 packed helpers (sm_100+) ----
__device__ __forceinline__ uint64_t pack2(float lo, float hi) {
    uint64_t r; asm("mov.b64 %0, {%1, %2};" : "=l"(r) : "f"(lo), "f"(hi)); return r;
}
__device__ __forceinline__ uint64_t dup2(float v) { return pack2(v, v); }
__device__ __forceinline__ void unpack2(uint64_t v, float& lo, float& hi) {
    asm("mov.b64 {%0, %1}, %2;" : "=f"(lo), "=f"(hi) : "l"(v));
}
__device__ __forceinline__ uint64_t fma2(uint64_t a, uint64_t b, uint64_t c) {
    uint64_t d; asm("fma.rn.f32x2 %0, %1, %2, %3;" : "=l"(d) : "l"(a), "l"(b), "l"(c)); return d;
}
__device__ __forceinline__ uint64_t mul2(uint64_t a, uint64_t b) {
    uint64_t d; asm("mul.rn.f32x2 %0, %1, %2;" : "=l"(d) : "l"(a), "l"(b)); return d;
}

// Fused up-2x (12-tap polyphase) -> LeakyReLU(0.1) -> down-2x, f32x2-packed,
// smem-free: each thread LDGs its own 24-float window (3x overlap hits in L1).
//   lane0 = E chain (even up phase), lane1 = O chain (odd up phase).
//   lrelu(v) = 0.55*v + 0.45*|v|
__global__ __launch_bounds__(NTHREADS)
void aa_act_kernel(const float* __restrict__ x,
                   const float* __restrict__ upf,
                   const float* __restrict__ dnf,
                   float* __restrict__ out)
{
    const int row = blockIdx.y;
    const int o   = blockIdx.x * TILE + threadIdx.x * CHUNK;   // in [0, LROW-8]
    const float* xr = x + (size_t)row * LROW;

    // Packed taps: f2[e] = (2*up[2e], 2*up[2e+1]);  dnp[m] = (dn[2m+1], dn[2m]).
    uint64_t f2[6], dnp[6];
#pragma unroll
    for (int e = 0; e < 6; ++e)
        f2[e] = pack2(2.0f * __ldg(upf + 2 * e), 2.0f * __ldg(upf + 2 * e + 1));
#pragma unroll
    for (int m = 0; m < 6; ++m)
        dnp[m] = pack2(__ldg(dnf + 2 * m + 1), __ldg(dnf + 2 * m));

    // Window x[o-8 .. o+15] -> lane-duplicated packs xx[j].
    uint64_t xx[24];
    if ((o != 0) & (o != LROW - CHUNK)) {
        // Interior thread: 6 aligned LDG.128 ((o-8)*4 is a multiple of 32B-16 -> 16B aligned).
        const float4* p = (const float4*)(xr + (o - 8));
#pragma unroll
        for (int v = 0; v < 6; ++v) {
            float4 q = __ldg(p + v);
            xx[4 * v + 0] = dup2(q.x); xx[4 * v + 1] = dup2(q.y);
            xx[4 * v + 2] = dup2(q.z); xx[4 * v + 3] = dup2(q.w);
        }
    } else {
        // Row-edge thread (2 per row): scalar loads with x edge clamp.
#pragma unroll
        for (int j = 0; j < 24; ++j) {
            int gi = o - 8 + j;
            gi = max(0, min(gi, LROW - 1));
            xx[j] = dup2(__ldg(xr + gi));
        }
    }

    // Up-sample + lrelu, packed.  EO[t] = (E[t], O[t]),
    //   E[t]==act[2*(o-2+t)], O[t]==act[2*(o-3+t)+1]; window xx[t+3 .. t+8].
    const uint64_t c55 = dup2(0.55f), c45 = dup2(0.45f);
    uint64_t EO[13];
#pragma unroll
    for (int t = 0; t < 13; ++t) {
        uint64_t v = mul2(f2[0], xx[t + 3]);
#pragma unroll
        for (int e = 1; e < 6; ++e)
            v = fma2(f2[e], xx[t + 3 + e], v);
        uint64_t av = v & 0x7FFFFFFF7FFFFFFFULL;      // packed |v|
        EO[t] = fma2(c45, av, mul2(c55, v));          // packed lrelu
    }

    // Row-edge act-index fixups (act index clamps to act[0] / act[2L-1]).
    if (o == 0) {
        float a0 = __uint_as_float((uint32_t)EO[2]);          // E[2] == act[0]
        uint64_t p = dup2(a0);
        EO[0] = p; EO[1] = p; EO[2] = p;
    }
    if (o == LROW - CHUNK) {
        float aL = __uint_as_float((uint32_t)(EO[10] >> 32)); // O[10] == act[2L-1]
        uint64_t p = dup2(aL);
        EO[10] = p; EO[11] = p; EO[12] = p;
    }

    // Downsample: out[o+q] = sum_m dn[2m]*O[q+m] + dn[2m+1]*E[q+m]
    float acc[CHUNK];
#pragma unroll
    for (int q = 0; q < CHUNK; ++q) {
        uint64_t a2 = mul2(dnp[0], EO[q]);
#pragma unroll
        for (int m = 1; m < 6; ++m)
            a2 = fma2(dnp[m], EO[q + m], a2);
        float lo, hi; unpack2(a2, lo, hi);
        acc[q] = lo + hi;
    }

    float4* op = (float4*)(out + (size_t)row * LROW + o);
    op[0] = make_float4(acc[0], acc[1], acc[2], acc[3]);
    op[1] = make_float4(acc[4], acc[5], acc[6], acc[7]);
}

extern "C" void kernel_launch(void* const* d_in, const int* in_sizes, int n_in,
                              void* d_out, int out_size)
{
    const float* x   = (const float*)d_in[0];
    const float* upf = (const float*)d_in[1];
    const float* dnf = (const float*)d_in[2];
    float* out = (float*)d_out;

    const int rows = in_sizes[0] / LROW;           // 8*128 = 1024
    dim3 grid(LROW / TILE, rows);
    aa_act_kernel<<<grid, NTHREADS>>>(x, upf, dnf, out);
}

// round 5
// speedup vs baseline: 1.8497x; 1.0433x over previous
#include <cuda_runtime.h>
#include <cstdint>

#define LROW     32768
#define TILE     2048
#define NTILES   (LROW / TILE)        // 16
#define NTHREADS 256
#define CHUNK    8
#define CTAS     888                  // 148 SMs x 6 resident CTAs, persistent

// ---- f32x2 packed helpers (sm_100+) ----
__device__ __forceinline__ uint64_t pack2(float lo, float hi) {
    uint64_t r; asm("mov.b64 %0, {%1, %2};" : "=l"(r) : "f"(lo), "f"(hi)); return r;
}
__device__ __forceinline__ uint64_t dup2(float v) { return pack2(v, v); }
__device__ __forceinline__ void unpack2(uint64_t v, float& lo, float& hi) {
    asm("mov.b64 {%0, %1}, %2;" : "=f"(lo), "=f"(hi) : "l"(v));
}
__device__ __forceinline__ uint64_t fma2(uint64_t a, uint64_t b, uint64_t c) {
    uint64_t d; asm("fma.rn.f32x2 %0, %1, %2, %3;" : "=l"(d) : "l"(a), "l"(b), "l"(c)); return d;
}
__device__ __forceinline__ uint64_t mul2(uint64_t a, uint64_t b) {
    uint64_t d; asm("mul.rn.f32x2 %0, %1, %2;" : "=l"(d) : "l"(a), "l"(b)); return d;
}

// Fused up-2x (12-tap polyphase) -> LeakyReLU(0.1) -> down-2x, f32x2-packed,
// smem-free, PERSISTENT: 888 CTAs loop over all (row, tile) pairs.
//   lane0 = E chain (even up phase), lane1 = O chain (odd up phase).
//   lrelu(v) = 0.55*v + 0.45*|v|
__global__ __launch_bounds__(NTHREADS, 6)
void aa_act_kernel(const float* __restrict__ x,
                   const float* __restrict__ upf,
                   const float* __restrict__ dnf,
                   float* __restrict__ out,
                   int total_tiles)
{
    // Packed taps, loaded once per CTA lifetime (uniform).
    uint64_t f2[6], dnp[6];
#pragma unroll
    for (int e = 0; e < 6; ++e)
        f2[e] = pack2(2.0f * __ldg(upf + 2 * e), 2.0f * __ldg(upf + 2 * e + 1));
#pragma unroll
    for (int m = 0; m < 6; ++m)
        dnp[m] = pack2(__ldg(dnf + 2 * m + 1), __ldg(dnf + 2 * m));
    const uint64_t c55 = dup2(0.55f), c45 = dup2(0.45f);

    for (int tile = blockIdx.x; tile < total_tiles; tile += CTAS) {
        const int row = tile >> 4;                         // NTILES = 16
        const int o   = (tile & (NTILES - 1)) * TILE + threadIdx.x * CHUNK;
        const float* xr = x + (size_t)row * LROW;

        // Window x[o-8 .. o+15] -> lane-duplicated packs xx[j].
        uint64_t xx[24];
        if ((o != 0) & (o != LROW - CHUNK)) {
            const float4* p = (const float4*)(xr + (o - 8));   // 16B aligned
#pragma unroll
            for (int v = 0; v < 6; ++v) {
                float4 q = __ldg(p + v);
                xx[4 * v + 0] = dup2(q.x); xx[4 * v + 1] = dup2(q.y);
                xx[4 * v + 2] = dup2(q.z); xx[4 * v + 3] = dup2(q.w);
            }
        } else {
            // Row-edge thread (2 per row): scalar loads with x edge clamp.
#pragma unroll
            for (int j = 0; j < 24; ++j) {
                int gi = o - 8 + j;
                gi = max(0, min(gi, LROW - 1));
                xx[j] = dup2(__ldg(xr + gi));
            }
        }

        // Up-sample + lrelu, packed.  EO[t] = (E[t], O[t]),
        //   E[t]==act[2*(o-2+t)], O[t]==act[2*(o-3+t)+1]; window xx[t+3 .. t+8].
        uint64_t EO[13];
#pragma unroll
        for (int t = 0; t < 13; ++t) {
            uint64_t v = mul2(f2[0], xx[t + 3]);
#pragma unroll
            for (int e = 1; e < 6; ++e)
                v = fma2(f2[e], xx[t + 3 + e], v);
            uint64_t av = v & 0x7FFFFFFF7FFFFFFFULL;      // packed |v|
            EO[t] = fma2(c45, av, mul2(c55, v));          // packed lrelu
        }

        // Row-edge act-index fixups (act index clamps to act[0] / act[2L-1]).
        if (o == 0) {
            float a0 = __uint_as_float((uint32_t)EO[2]);          // E[2] == act[0]
            uint64_t p = dup2(a0);
            EO[0] = p; EO[1] = p; EO[2] = p;
        }
        if (o == LROW - CHUNK) {
            float aL = __uint_as_float((uint32_t)(EO[10] >> 32)); // O[10] == act[2L-1]
            uint64_t p = dup2(aL);
            EO[10] = p; EO[11] = p; EO[12] = p;
        }

        // Downsample: out[o+q] = sum_m dn[2m]*O[q+m] + dn[2m+1]*E[q+m]
        float acc[CHUNK];
#pragma unroll
        for (int q = 0; q < CHUNK; ++q) {
            uint64_t a2 = mul2(dnp[0], EO[q]);
#pragma unroll
            for (int m = 1; m < 6; ++m)
                a2 = fma2(dnp[m], EO[q + m], a2);
            float lo, hi; unpack2(a2, lo, hi);
            acc[q] = lo + hi;
        }

        float4* op = (float4*)(out + (size_t)row * LROW + o);
        op[0] = make_float4(acc[0], acc[1], acc[2], acc[3]);
        op[1] = make_float4(acc[4], acc[5], acc[6], acc[7]);
    }
}

extern "C" void kernel_launch(void* const* d_in, const int* in_sizes, int n_in,
                              void* d_out, int out_size)
{
    const float* x   = (const float*)d_in[0];
    const float* upf = (const float*)d_in[1];
    const float* dnf = (const float*)d_in[2];
    float* out = (float*)d_out;

    const int rows = in_sizes[0] / LROW;           // 8*128 = 1024
    const int total_tiles = rows * NTILES;         // 16384
    aa_act_kernel<<<CTAS, NTHREADS>>>(x, upf, dnf, out, total_tiles);
}